// round 12
// baseline (speedup 1.0000x reference)
#include <cuda_runtime.h>
#include <cuda_bf16.h>
#include <math.h>
#include <stdint.h>

#define BATCH 16
#define CH    512
#define HW    4096
#define HID   32
#define KSEL  153
#define OUT_HALF ((long)BATCH*CH*HW)

#define STAGES 4
#define BSN    136                  /* B smem n-stride (uint32 units)     */
#define ASTG   8192                 /* A stage bytes: 2 subtiles x 4096   */
#define BSTG   (16*BSN*4)           /* B stage bytes = 8704               */
#define STGB   (ASTG + BSTG)        /* 16896 per stage                    */
#define SMEM_BYTES (STAGES*STGB)    /* 67584                              */

__device__ __nv_bfloat16 g_Wb[CH*CH];       /* softmax rows, bf16, k-permuted */
__device__ uint32_t g_xbt[(long)BATCH*256*HW];  /* x_t bf16 pair-interleaved */
__device__ uint32_t g_xbc[(long)BATCH*256*HW];  /* x_c bf16 pair-interleaved */
__device__ float g_mean_t[BATCH*CH];
__device__ float g_mean_c[BATCH*CH];
__device__ float g_att_t[BATCH*CH];
__device__ float g_att_c[BATCH*CH];
__device__ int   g_gidx[BATCH*256];
__device__ int   g_rem [BATCH*256];

__device__ __forceinline__ uint32_t packbf(float lo, float hi) {
    uint32_t u;
    asm("cvt.rn.bf16x2.f32 %0, %1, %2;" : "=r"(u) : "f"(hi), "f"(lo));
    return u;
}

/* ------- 1. spatial means + bf16 pair-interleaved copy ------- */
__global__ void mean_kernel(const float* __restrict__ xt,
                            const float* __restrict__ xc) {
    int pr = blockIdx.x * 8 + (threadIdx.x >> 5);   /* 0..8191 */
    int lane = threadIdx.x & 31;
    int which = pr >> 12, r2 = pr & 4095;
    const float* src = which ? xc : xt;
    const float4* pa = (const float4*)(src + (long)(2*r2) * HW);
    const float4* pb = pa + HW/4;
    uint4* po = (uint4*)((which ? g_xbc : g_xbt) + (long)r2 * HW);
    float s0 = 0.f, s1 = 0.f;
    #pragma unroll
    for (int i = 0; i < 32; i++) {
        float4 a = pa[lane + 32*i];
        float4 b = pb[lane + 32*i];
        s0 += (a.x + a.y) + (a.z + a.w);
        s1 += (b.x + b.y) + (b.z + b.w);
        uint4 o;
        o.x = packbf(a.x, b.x);
        o.y = packbf(a.y, b.y);
        o.z = packbf(a.z, b.z);
        o.w = packbf(a.w, b.w);
        po[lane + 32*i] = o;
    }
    for (int o = 16; o; o >>= 1) {
        s0 += __shfl_xor_sync(0xffffffffu, s0, o);
        s1 += __shfl_xor_sync(0xffffffffu, s1, o);
    }
    if (lane == 0) {
        float* dst = which ? g_mean_c : g_mean_t;
        dst[2*r2]     = s0 * (1.f/HW);
        dst[2*r2 + 1] = s1 * (1.f/HW);
    }
}

/* ---------------- 2. SE MLPs + top-k lists ---------------- */
__global__ void se_kernel(const float* __restrict__ w1_t, const float* __restrict__ b1_t,
                          const float* __restrict__ w2_t, const float* __restrict__ b2_t,
                          const float* __restrict__ w1_c, const float* __restrict__ b1_c,
                          const float* __restrict__ w2_c, const float* __restrict__ b2_c) {
    int b = blockIdx.x, tid = threadIdx.x;   /* 512 threads */
    int warp = tid >> 5, lane = tid & 31;
    __shared__ float m[2][CH];
    __shared__ float h[2][HID];
    __shared__ float at[CH];
    __shared__ int   msk[CH];
    m[0][tid] = g_mean_t[b*CH + tid];
    m[1][tid] = g_mean_c[b*CH + tid];
    __syncthreads();
    for (int q = warp; q < 64; q += 16) {
        int br = q >> 5, j = q & 31;
        const float* w1 = br ? w1_c : w1_t;
        float s = 0.f;
        for (int i = lane; i < CH; i += 32) s += m[br][i] * w1[i*HID + j];
        for (int o = 16; o; o >>= 1) s += __shfl_xor_sync(0xffffffffu, s, o);
        if (lane == 0) h[br][j] = fmaxf(s + (br ? b1_c : b1_t)[j], 0.f);
    }
    __syncthreads();
    {
        float s0 = b2_t[tid], s1 = b2_c[tid];
        #pragma unroll
        for (int j = 0; j < HID; j++) {
            s0 += h[0][j] * w2_t[j*CH + tid];
            s1 += h[1][j] * w2_c[j*CH + tid];
        }
        float a0 = 1.f/(1.f + expf(-s0)), a1 = 1.f/(1.f + expf(-s1));
        at[tid] = a0;
        g_att_t[b*CH + tid] = a0;
        g_att_c[b*CH + tid] = a1;
    }
    __syncthreads();
    int sel;
    {
        float v = at[tid];
        int rank = 0;
        for (int j = 0; j < CH; j++) {
            float u = at[j];
            rank += (u > v) || (u == v && j < tid);
        }
        sel = (rank < KSEL);
        msk[tid] = sel;
    }
    __syncthreads();
    {
        int pre = 0;
        for (int j = 0; j < tid; j++) pre += msk[j];
        if (sel) g_gidx[b*256 + pre] = tid;
        else {
            int np = tid - pre;
            if (np < 256 - KSEL) g_gidx[b*256 + KSEL + np] = tid;
            else                 g_rem [b*256 + np - (256 - KSEL)] = tid;
        }
    }
}

/* ---------------- 3. softmax -> bf16 permuted g_Wb ---------------- */
__device__ __forceinline__ int kperm(int c) {
    return (c & ~15) | ((((c >> 1) & 3) << 2) | (((c >> 3) & 1) << 1) | (c & 1));
}
__global__ void softmax_kernel(const float* __restrict__ ca) {
    int r = blockIdx.x, tid = threadIdx.x;   /* 256 */
    __shared__ float red[8];
    float v0 = ca[r*CH + tid], v1 = ca[r*CH + 256 + tid];
    float mx = fmaxf(v0, v1);
    for (int o = 16; o; o >>= 1) mx = fmaxf(mx, __shfl_xor_sync(0xffffffffu, mx, o));
    if ((tid & 31) == 0) red[tid >> 5] = mx;
    __syncthreads();
    float m2 = red[0];
    #pragma unroll
    for (int i = 1; i < 8; i++) m2 = fmaxf(m2, red[i]);
    float e0 = expf(v0 - m2), e1 = expf(v1 - m2);
    float s = e0 + e1;
    for (int o = 16; o; o >>= 1) s += __shfl_xor_sync(0xffffffffu, s, o);
    __syncthreads();
    if ((tid & 31) == 0) red[tid >> 5] = s;
    __syncthreads();
    float tot = 0.f;
    #pragma unroll
    for (int i = 0; i < 8; i++) tot += red[i];
    float inv = 1.f / tot;
    g_Wb[r*CH + kperm(tid)]       = __float2bfloat16(e0 * inv);
    g_Wb[r*CH + kperm(tid + 256)] = __float2bfloat16(e1 * inv);
}

/* ---------------- 4. remainder rows: out_t = att*x ---------------- */
__global__ void rem_kernel(const float* __restrict__ xt, float* __restrict__ out) {
    int b = blockIdx.x >> 8, i = blockIdx.x & 255;
    int ch = g_rem[b*256 + i];
    float a = g_att_t[b*CH + ch];
    const float4* src = (const float4*)(xt + ((long)b*CH + ch)*HW);
    float4* dst = (float4*)(out + ((long)b*CH + ch)*HW);
    #pragma unroll
    for (int k = 0; k < 4; k++) {
        float4 v = src[threadIdx.x + 256*k];
        v.x *= a; v.y *= a; v.z *= a; v.w *= a;
        dst[threadIdx.x + 256*k] = v;
    }
}

/* -------- 5. fused bf16 GEMM: conflict-free A swizzle -------- */
__global__ __launch_bounds__(256, 2)
void gemm_fused(const float* __restrict__ xt,
                const float* __restrict__ xc,
                float* __restrict__ out) {
    extern __shared__ char smem[];
    __shared__ int gtab[128];

    const int tid  = threadIdx.x;
    const int lane = tid & 31, warp = tid >> 5;
    const int g = lane >> 2, tg = lane & 3;
    const int wm = (warp >> 2) * 64;
    const int wn = (warp & 3)  * 32;

    const int bid = blockIdx.x;
    const int tH  = bid < 1024;
    int panel, bm;
    if (tH) { panel = bid >> 1;          bm = (bid & 1) * 128; }
    else    { int q = bid - 1024; panel = q >> 2; bm = (q & 3) * 128; }
    const int bb = panel >> 5, p0 = (panel & 31) * 128;
    const uint32_t* bsrc2 = (tH ? g_xbc : g_xbt) + (long)bb*256*HW + p0;
    const float* xe = tH ? xt : xc;
    float*       op = out + (tH ? 0 : OUT_HALF);

    if (tid < 128) gtab[tid] = tH ? g_gidx[bb*256 + bm + tid] : (bm + tid);
    __syncthreads();

    /* A loader: row = tid>>1, half = tid&1; swizzle incl. row bit 2 */
    const int arow = tid >> 1, ah = tid & 1;
    const __nv_bfloat16* aptr = g_Wb + (long)gtab[arow]*CH + ah*8;
    const int aswz = (arow & 3) ^ ((arow & 4) >> 1);
    const unsigned asw0 = arow*32 + (((2*ah)     ^ aswz) * 8);
    const unsigned asw1 = arow*32 + (((2*ah + 1) ^ aswz) * 8);

    /* B loader: 16 pair-rows x 512B per stage; 2 x 16B per thread */
    const int b2row = tid >> 4;            /* 0..15 */
    const int b2col = (tid & 15) * 8;      /* uint32 units */
    const unsigned smbase = (unsigned)__cvta_generic_to_shared(smem);

    auto issue = [&](int st) {
        const int p = st % STAGES;
        const unsigned ab  = smbase + p*STGB;
        const unsigned bbs = ab + ASTG;
        const int k0 = st * 32;
        #pragma unroll
        for (int j = 0; j < 2; j++) {
            const __nv_bfloat16* sA = aptr + k0 + j*16;
            asm volatile("cp.async.ca.shared.global [%0], [%1], 8;\n"
                         :: "r"(ab + j*4096 + asw0), "l"(sA) : "memory");
            asm volatile("cp.async.ca.shared.global [%0], [%1], 8;\n"
                         :: "r"(ab + j*4096 + asw1), "l"(sA + 4) : "memory");
        }
        const uint32_t* bp = bsrc2 + (long)(st*16 + b2row)*HW + b2col;
        const unsigned bd = bbs + (b2row*BSN + b2col)*4;
        asm volatile("cp.async.cg.shared.global [%0], [%1], 16;\n"
                     :: "r"(bd), "l"(bp) : "memory");
        asm volatile("cp.async.cg.shared.global [%0], [%1], 16;\n"
                     :: "r"(bd + 16), "l"(bp + 4) : "memory");
    };

    float acc[4][4][4];
    #pragma unroll
    for (int i = 0; i < 4; i++)
        #pragma unroll
        for (int j = 0; j < 4; j++)
            #pragma unroll
            for (int k = 0; k < 4; k++) acc[i][j][k] = 0.f;

    issue(0); asm volatile("cp.async.commit_group;\n" ::: "memory");
    issue(1); asm volatile("cp.async.commit_group;\n" ::: "memory");
    issue(2); asm volatile("cp.async.commit_group;\n" ::: "memory");

    /* A fragment read swizzle: slot = tg ^ (g&3) ^ ((g&4)>>1) */
    const int xa = ((tg ^ (g & 3) ^ ((g & 4) >> 1)) * 8);

    for (int st = 0; st < 16; st++) {
        asm volatile("cp.async.wait_group 2;\n" ::: "memory");
        __syncthreads();
        if (st < 13) issue(st + 3);
        asm volatile("cp.async.commit_group;\n" ::: "memory");

        const int p = st % STAGES;
        const char*     Asb = smem + p*STGB;
        const uint32_t* Bsb = (const uint32_t*)(Asb + ASTG);

        #pragma unroll
        for (int j = 0; j < 2; j++) {
            unsigned bf[4][2];
            #pragma unroll
            for (int nt = 0; nt < 4; nt++) {
                int col = wn + nt*8 + g;
                bf[nt][0] = Bsb[(j*8 + tg    )*BSN + col];
                bf[nt][1] = Bsb[(j*8 + tg + 4)*BSN + col];
            }
            const char* Aj = Asb + j*4096;
            #pragma unroll
            for (int mt = 0; mt < 4; mt++) {
                int row = wm + mt*16 + g;
                uint2 lo = *(const uint2*)(Aj + row*32 + xa);
                uint2 hi = *(const uint2*)(Aj + (row+8)*32 + xa);
                #pragma unroll
                for (int nt = 0; nt < 4; nt++) {
                    asm volatile(
                        "mma.sync.aligned.m16n8k16.row.col.f32.bf16.bf16.f32 "
                        "{%0,%1,%2,%3}, {%4,%5,%6,%7}, {%8,%9}, {%0,%1,%2,%3};\n"
                        : "+f"(acc[mt][nt][0]), "+f"(acc[mt][nt][1]),
                          "+f"(acc[mt][nt][2]), "+f"(acc[mt][nt][3])
                        : "r"(lo.x), "r"(hi.x), "r"(lo.y), "r"(hi.y),
                          "r"(bf[nt][0]), "r"(bf[nt][1]));
                }
            }
        }
    }

    /* ---------------- epilogue: o = fs*x + fc*d ---------------- */
    const float* attp = (tH ? g_att_t : g_att_c) + bb*CH;

    #pragma unroll
    for (int mt = 0; mt < 4; mt++) {
        #pragma unroll
        for (int h2 = 0; h2 < 2; h2++) {
            int  local = wm + mt*16 + g + h2*8;
            int  ch    = gtab[local];
            float fs   = attp[ch];
            float fc   = tH ? ((bm + local) < KSEL ? 1.f : 0.f) : fs;
            long base  = ((long)bb*CH + ch)*HW + p0;
            #pragma unroll
            for (int nt = 0; nt < 4; nt++) {
                int  col = wn + nt*8 + 2*tg;
                long idx = base + col;
                float2 xv = *(const float2*)(xe + idx);
                float2 o;
                o.x = fs * xv.x + fc * acc[mt][nt][h2*2 + 0];
                o.y = fs * xv.y + fc * acc[mt][nt][h2*2 + 1];
                *(float2*)(op + idx) = o;
            }
        }
    }
}

/* ---------------- launch ---------------- */
extern "C" void kernel_launch(void* const* d_in, const int* in_sizes, int n_in,
                              void* d_out, int out_size) {
    const float* x_t  = (const float*)d_in[0];
    const float* x_c  = (const float*)d_in[1];
    const float* w1_t = (const float*)d_in[2];
    const float* b1_t = (const float*)d_in[3];
    const float* w2_t = (const float*)d_in[4];
    const float* b2_t = (const float*)d_in[5];
    const float* w1_c = (const float*)d_in[6];
    const float* b1_c = (const float*)d_in[7];
    const float* w2_c = (const float*)d_in[8];
    const float* b2_c = (const float*)d_in[9];
    const float* ca   = (const float*)d_in[10];
    float* out = (float*)d_out;

    static int init = 0;
    if (!init) {
        cudaFuncSetAttribute(gemm_fused,
                             cudaFuncAttributeMaxDynamicSharedMemorySize, SMEM_BYTES);
        init = 1;
    }
    mean_kernel<<<1024, 256>>>(x_t, x_c);
    softmax_kernel<<<CH, 256>>>(ca);
    se_kernel<<<BATCH, 512>>>(w1_t, b1_t, w2_t, b2_t, w1_c, b1_c, w2_c, b2_c);
    rem_kernel<<<BATCH*256, 256>>>(x_t, out);
    gemm_fused<<<3072, 256, SMEM_BYTES>>>(x_t, x_c, out);
}